// round 7
// baseline (speedup 1.0000x reference)
#include <cuda_runtime.h>
#include <math.h>

// Problem constants (fixed shapes from reference setup_inputs)
#define NB 4
#define ND 512
#define NLSEQ 4096
#define NCAT 1168
#define NLBL 8929

// --------------------------------------------------------------------------
// Scratch (device globals: allocation-free per harness rules)
// --------------------------------------------------------------------------
__device__ float g_K  [(size_t)NB * ND * NLSEQ];    // Kt[b][d][l]  32 MB
__device__ float g_V  [(size_t)NB * ND * NLSEQ];    // Vt[b][d][l]  32 MB
__device__ float g_E1 [(size_t)NB * NCAT * NLSEQ];  // E1/A1        73 MB
__device__ float g_C1 [(size_t)NB * NCAT * ND];     // C1           9.1 MB
__device__ float g_Q2b[(size_t)NB * NLBL * ND];     // Q2 + gather  70 MB

// --------------------------------------------------------------------------
// SGEMM: C[m,n] = epi( sum_k A[m,k] * B[.,.] )
//   BT=false : B is [K,N] row-major (ldb = row stride)      -> "NN"
//   BT=true  : B is [N,K] row-major (ldb = row stride)      -> "NT"
// epi: 0 = none, 1 = *alpha, 2 = +bias[row] then ELU
// Block 128x128, K-step 8, 256 threads, 8x8 per-thread microtile.
// N and K must be multiples of 128 / 8 (true for all call sites); M guarded.
// --------------------------------------------------------------------------
#define BM 128
#define BN 128
#define BK 8
#define TM 8
#define TN 8
#define SPAD 4

template <bool BT>
__global__ __launch_bounds__(256, 2)
void sgemm(const float* __restrict__ Ag, const float* __restrict__ Bg,
           float* __restrict__ Cg,
           int M, int N, int K, int lda, int ldb, int ldc,
           long long sA, long long sB, long long sC,
           float alpha, const float* __restrict__ bias, int epi)
{
    __shared__ float As[BK][BM + SPAD];
    __shared__ float Bs[BK][BN + SPAD];

    const float* A = Ag + (long long)blockIdx.z * sA;
    const float* Bp = Bg + (long long)blockIdx.z * sB;
    float*       C = Cg + (long long)blockIdx.z * sC;

    const int m0 = blockIdx.y * BM;
    const int n0 = blockIdx.x * BN;
    const int tid = threadIdx.x;
    const int tx = tid & 15;      // 0..15 -> N
    const int ty = tid >> 4;      // 0..15 -> M

    float acc[TM][TN] = {};

    // ---- A tile load mapping: 128 rows x 8 k, float4/thread ----
    const int arow = tid >> 1;          // 0..127
    const int acol = (tid & 1) * 4;     // 0 or 4
    const bool aval = (m0 + arow) < M;
    const float* Aptr = A + (long long)(m0 + arow) * lda + acol;

    // ---- B tile load mapping ----
    const float* Bptr;
    int brow, bcol;
    if (BT) {   // B[N][K]: transpose-load like A
        brow = tid >> 1;               // n 0..127
        bcol = (tid & 1) * 4;          // k 0 or 4
        Bptr = Bp + (long long)(n0 + brow) * ldb + bcol;
    } else {    // B[K][N]: direct
        brow = tid >> 5;               // k 0..7
        bcol = (tid & 31) * 4;         // n
        Bptr = Bp + (long long)brow * ldb + n0 + bcol;
    }

    for (int k0 = 0; k0 < K; k0 += BK) {
        float4 av = aval ? *(const float4*)(Aptr + k0)
                         : make_float4(0.f, 0.f, 0.f, 0.f);
        float4 bv;
        if (BT) bv = *(const float4*)(Bptr + k0);
        else    bv = *(const float4*)(Bptr + (long long)k0 * ldb);

        __syncthreads();   // previous tile fully consumed
        As[acol + 0][arow] = av.x;
        As[acol + 1][arow] = av.y;
        As[acol + 2][arow] = av.z;
        As[acol + 3][arow] = av.w;
        if (BT) {
            Bs[bcol + 0][brow] = bv.x;
            Bs[bcol + 1][brow] = bv.y;
            Bs[bcol + 2][brow] = bv.z;
            Bs[bcol + 3][brow] = bv.w;
        } else {
            *(float4*)&Bs[brow][bcol] = bv;
        }
        __syncthreads();

        #pragma unroll
        for (int kk = 0; kk < BK; kk++) {
            float af[TM], bf[TN];
            *(float4*)&af[0] = *(const float4*)&As[kk][ty * TM];
            *(float4*)&af[4] = *(const float4*)&As[kk][ty * TM + 4];
            *(float4*)&bf[0] = *(const float4*)&Bs[kk][tx * TN];
            *(float4*)&bf[4] = *(const float4*)&Bs[kk][tx * TN + 4];
            #pragma unroll
            for (int i = 0; i < TM; i++)
                #pragma unroll
                for (int j = 0; j < TN; j++)
                    acc[i][j] = fmaf(af[i], bf[j], acc[i][j]);
        }
    }

    // ---- epilogue ----
    #pragma unroll
    for (int i = 0; i < TM; i++) {
        const int row = m0 + ty * TM + i;
        if (row >= M) continue;
        const float bval = (epi == 2) ? bias[row] : 0.f;
        float* crow = C + (long long)row * ldc + n0 + tx * TN;
        #pragma unroll
        for (int j = 0; j < TN; j += 4) {
            float t0 = acc[i][j + 0], t1 = acc[i][j + 1];
            float t2 = acc[i][j + 2], t3 = acc[i][j + 3];
            if (epi == 1) {
                t0 *= alpha; t1 *= alpha; t2 *= alpha; t3 *= alpha;
            } else if (epi == 2) {
                t0 += bval; t1 += bval; t2 += bval; t3 += bval;
                t0 = t0 > 0.f ? t0 : expm1f(t0);
                t1 = t1 > 0.f ? t1 : expm1f(t1);
                t2 = t2 > 0.f ? t2 : expm1f(t2);
                t3 = t3 > 0.f ? t3 : expm1f(t3);
            }
            *(float4*)(crow + j) = make_float4(t0, t1, t2, t3);
        }
    }
}

// --------------------------------------------------------------------------
// In-place row softmax, row length 4096, one CTA (256 thr) per row.
// --------------------------------------------------------------------------
__global__ void softmax_inplace(float* __restrict__ E)
{
    float4* rp = (float4*)(E + (long long)blockIdx.x * NLSEQ);
    const int tid = threadIdx.x;
    __shared__ float red[256];

    float v[16];
    float m = -INFINITY;
    #pragma unroll
    for (int i = 0; i < 4; i++) {
        float4 x = rp[tid + i * 256];
        v[i * 4 + 0] = x.x; v[i * 4 + 1] = x.y;
        v[i * 4 + 2] = x.z; v[i * 4 + 3] = x.w;
        m = fmaxf(m, fmaxf(fmaxf(x.x, x.y), fmaxf(x.z, x.w)));
    }
    red[tid] = m;
    __syncthreads();
    for (int s = 128; s > 0; s >>= 1) {
        if (tid < s) red[tid] = fmaxf(red[tid], red[tid + s]);
        __syncthreads();
    }
    m = red[0];
    __syncthreads();

    float sum = 0.f;
    #pragma unroll
    for (int i = 0; i < 16; i++) {
        v[i] = expf(v[i] - m);
        sum += v[i];
    }
    red[tid] = sum;
    __syncthreads();
    for (int s = 128; s > 0; s >>= 1) {
        if (tid < s) red[tid] += red[tid + s];
        __syncthreads();
    }
    const float inv = 1.f / red[0];

    #pragma unroll
    for (int i = 0; i < 4; i++)
        rp[tid + i * 256] = make_float4(v[i * 4 + 0] * inv, v[i * 4 + 1] * inv,
                                        v[i * 4 + 2] * inv, v[i * 4 + 3] * inv);
}

// --------------------------------------------------------------------------
// Q2b[b,n,:] = Q2[n,:] + C1[b, map[n], :]   (grid: (NLBL, NB), 128 thr float4)
// --------------------------------------------------------------------------
__global__ void build_q2b(const float* __restrict__ Q2, const float* __restrict__ C1,
                          const int* __restrict__ cmap, float* __restrict__ q2b)
{
    const int n = blockIdx.x, b = blockIdx.y, t = threadIdx.x;
    const int c = cmap[n];
    const float4* q  = (const float4*)(Q2 + (long long)n * ND);
    const float4* cc = (const float4*)(C1 + ((long long)b * NCAT + c) * ND);
    float4*       o  = (float4*)(q2b + ((long long)b * NLBL + n) * ND);
    float4 a = q[t], d = cc[t];
    o[t] = make_float4(a.x + d.x, a.y + d.y, a.z + d.z, a.w + d.w);
}

// --------------------------------------------------------------------------
// Launch
// --------------------------------------------------------------------------
extern "C" void kernel_launch(void* const* d_in, const int* in_sizes, int n_in,
                              void* d_out, int out_size)
{
    const float* H    = (const float*)d_in[0];   // [B, d, L]
    const float* Wk   = (const float*)d_in[1];   // [d, d]
    const float* bk   = (const float*)d_in[2];   // [d]
    const float* Wv   = (const float*)d_in[3];   // [d, d]
    const float* bv   = (const float*)d_in[4];   // [d]
    const float* Q1   = (const float*)d_in[5];   // [C1, d]
    const float* Q2   = (const float*)d_in[6];   // [Lbl, d]
    const int*   cmap = (const int*)d_in[7];     // [Lbl]
    (void)in_sizes; (void)n_in; (void)out_size;

    float *Kp, *Vp, *E1p, *C1p, *Q2bp;
    cudaGetSymbolAddress((void**)&Kp,   g_K);
    cudaGetSymbolAddress((void**)&Vp,   g_V);
    cudaGetSymbolAddress((void**)&E1p,  g_E1);
    cudaGetSymbolAddress((void**)&C1p,  g_C1);
    cudaGetSymbolAddress((void**)&Q2bp, g_Q2b);

    float* outC2 = (float*)d_out;                                   // [B, Lbl, d]
    float* outA2 = (float*)d_out + (long long)NB * NLBL * ND;       // [B, Lbl, L]

    const float inv_scale = 1.0f / sqrtf(512.0f);
    const long long sKV = (long long)ND * NLSEQ;

    // 1) Kt = elu(Wk @ H_b + bk), Vt likewise.  C: [d, L] per b (NN)
    {
        dim3 grid(NLSEQ / BN, ND / BM, NB);
        sgemm<false><<<grid, 256>>>(Wk, H, Kp, ND, NLSEQ, ND, ND, NLSEQ, NLSEQ,
                                    0, sKV, sKV, 1.f, bk, 2);
        sgemm<false><<<grid, 256>>>(Wv, H, Vp, ND, NLSEQ, ND, ND, NLSEQ, NLSEQ,
                                    0, sKV, sKV, 1.f, bv, 2);
    }
    // 2) E1 = (Q1 @ Kt) / SCALE   [NCAT, L] per b (NN)
    {
        dim3 grid(NLSEQ / BN, (NCAT + BM - 1) / BM, NB);
        sgemm<false><<<grid, 256>>>(Q1, Kp, E1p, NCAT, NLSEQ, ND, ND, NLSEQ, NLSEQ,
                                    0, sKV, (long long)NCAT * NLSEQ,
                                    inv_scale, nullptr, 1);
    }
    // 3) A1 = softmax(E1) in place
    softmax_inplace<<<NB * NCAT, 256>>>(E1p);
    // 4) C1 = A1 @ Vt^T   [NCAT, d] per b (NT)
    {
        dim3 grid(ND / BN, (NCAT + BM - 1) / BM, NB);
        sgemm<true><<<grid, 256>>>(E1p, Vp, C1p, NCAT, ND, NLSEQ,
                                   NLSEQ, NLSEQ, ND,
                                   (long long)NCAT * NLSEQ, sKV,
                                   (long long)NCAT * ND, 1.f, nullptr, 0);
    }
    // 5) Q2b = Q2 + C1[gather]
    build_q2b<<<dim3(NLBL, NB), 128>>>(Q2, C1p, cmap, Q2bp);
    // 6) E2 = (Q2b @ Kt)/SCALE -> written straight into A2 output region (NN)
    {
        dim3 grid(NLSEQ / BN, (NLBL + BM - 1) / BM, NB);
        sgemm<false><<<grid, 256>>>(Q2bp, Kp, outA2, NLBL, NLSEQ, ND,
                                    ND, NLSEQ, NLSEQ,
                                    (long long)NLBL * ND, sKV,
                                    (long long)NLBL * NLSEQ,
                                    inv_scale, nullptr, 1);
    }
    // 7) A2 = softmax(E2) in place (this IS the second output)
    softmax_inplace<<<NB * NLBL, 256>>>(outA2);
    // 8) C2 = A2 @ Vt^T   [NLBL, d] per b (NT)
    {
        dim3 grid(ND / BN, (NLBL + BM - 1) / BM, NB);
        sgemm<true><<<grid, 256>>>(outA2, Vp, outC2, NLBL, ND, NLSEQ,
                                   NLSEQ, NLSEQ, ND,
                                   (long long)NLBL * NLSEQ, sKV,
                                   (long long)NLBL * ND, 1.f, nullptr, 0);
    }
}

// round 8
// speedup vs baseline: 1.0001x; 1.0001x over previous
#include <cuda_runtime.h>
#include <math.h>

// Problem constants (fixed shapes from reference setup_inputs)
#define NB 4
#define ND 512
#define NLSEQ 4096
#define NCAT 1168
#define NLBL 8929

// --------------------------------------------------------------------------
// Scratch (device globals: allocation-free per harness rules)
// --------------------------------------------------------------------------
__device__ float g_K  [(size_t)NB * ND * NLSEQ];    // Kt[b][d][l]  32 MB
__device__ float g_V  [(size_t)NB * ND * NLSEQ];    // Vt[b][d][l]  32 MB
__device__ float g_E1 [(size_t)NB * NCAT * NLSEQ];  // E1/A1        73 MB
__device__ float g_C1 [(size_t)NB * NCAT * ND];     // C1           9.1 MB
__device__ float g_Q2b[(size_t)NB * NLBL * ND];     // Q2 + gather  70 MB

// --------------------------------------------------------------------------
// SGEMM: C[m,n] = epi( sum_k A[m,k] * B[.,.] )
//   BT=false : B is [K,N] row-major (ldb = row stride)      -> "NN"
//   BT=true  : B is [N,K] row-major (ldb = row stride)      -> "NT"
// epi: 0 = none, 1 = *alpha, 2 = +bias[row] then ELU
// Block 128x128, K-step 8, 256 threads, 8x8 per-thread microtile.
// N and K must be multiples of 128 / 8 (true for all call sites); M guarded.
// --------------------------------------------------------------------------
#define BM 128
#define BN 128
#define BK 8
#define TM 8
#define TN 8
#define SPAD 4

template <bool BT>
__global__ __launch_bounds__(256, 2)
void sgemm(const float* __restrict__ Ag, const float* __restrict__ Bg,
           float* __restrict__ Cg,
           int M, int N, int K, int lda, int ldb, int ldc,
           long long sA, long long sB, long long sC,
           float alpha, const float* __restrict__ bias, int epi)
{
    __shared__ float As[BK][BM + SPAD];
    __shared__ float Bs[BK][BN + SPAD];

    const float* A = Ag + (long long)blockIdx.z * sA;
    const float* Bp = Bg + (long long)blockIdx.z * sB;
    float*       C = Cg + (long long)blockIdx.z * sC;

    const int m0 = blockIdx.y * BM;
    const int n0 = blockIdx.x * BN;
    const int tid = threadIdx.x;
    const int tx = tid & 15;      // 0..15 -> N
    const int ty = tid >> 4;      // 0..15 -> M

    float acc[TM][TN] = {};

    // ---- A tile load mapping: 128 rows x 8 k, float4/thread ----
    const int arow = tid >> 1;          // 0..127
    const int acol = (tid & 1) * 4;     // 0 or 4
    const bool aval = (m0 + arow) < M;
    const float* Aptr = A + (long long)(m0 + arow) * lda + acol;

    // ---- B tile load mapping ----
    const float* Bptr;
    int brow, bcol;
    if (BT) {   // B[N][K]: transpose-load like A
        brow = tid >> 1;               // n 0..127
        bcol = (tid & 1) * 4;          // k 0 or 4
        Bptr = Bp + (long long)(n0 + brow) * ldb + bcol;
    } else {    // B[K][N]: direct
        brow = tid >> 5;               // k 0..7
        bcol = (tid & 31) * 4;         // n
        Bptr = Bp + (long long)brow * ldb + n0 + bcol;
    }

    for (int k0 = 0; k0 < K; k0 += BK) {
        float4 av = aval ? *(const float4*)(Aptr + k0)
                         : make_float4(0.f, 0.f, 0.f, 0.f);
        float4 bv;
        if (BT) bv = *(const float4*)(Bptr + k0);
        else    bv = *(const float4*)(Bptr + (long long)k0 * ldb);

        __syncthreads();   // previous tile fully consumed
        As[acol + 0][arow] = av.x;
        As[acol + 1][arow] = av.y;
        As[acol + 2][arow] = av.z;
        As[acol + 3][arow] = av.w;
        if (BT) {
            Bs[bcol + 0][brow] = bv.x;
            Bs[bcol + 1][brow] = bv.y;
            Bs[bcol + 2][brow] = bv.z;
            Bs[bcol + 3][brow] = bv.w;
        } else {
            *(float4*)&Bs[brow][bcol] = bv;
        }
        __syncthreads();

        #pragma unroll
        for (int kk = 0; kk < BK; kk++) {
            float af[TM], bf[TN];
            *(float4*)&af[0] = *(const float4*)&As[kk][ty * TM];
            *(float4*)&af[4] = *(const float4*)&As[kk][ty * TM + 4];
            *(float4*)&bf[0] = *(const float4*)&Bs[kk][tx * TN];
            *(float4*)&bf[4] = *(const float4*)&Bs[kk][tx * TN + 4];
            #pragma unroll
            for (int i = 0; i < TM; i++)
                #pragma unroll
                for (int j = 0; j < TN; j++)
                    acc[i][j] = fmaf(af[i], bf[j], acc[i][j]);
        }
    }

    // ---- epilogue ----
    #pragma unroll
    for (int i = 0; i < TM; i++) {
        const int row = m0 + ty * TM + i;
        if (row >= M) continue;
        const float bval = (epi == 2) ? bias[row] : 0.f;
        float* crow = C + (long long)row * ldc + n0 + tx * TN;
        #pragma unroll
        for (int j = 0; j < TN; j += 4) {
            float t0 = acc[i][j + 0], t1 = acc[i][j + 1];
            float t2 = acc[i][j + 2], t3 = acc[i][j + 3];
            if (epi == 1) {
                t0 *= alpha; t1 *= alpha; t2 *= alpha; t3 *= alpha;
            } else if (epi == 2) {
                t0 += bval; t1 += bval; t2 += bval; t3 += bval;
                t0 = t0 > 0.f ? t0 : expm1f(t0);
                t1 = t1 > 0.f ? t1 : expm1f(t1);
                t2 = t2 > 0.f ? t2 : expm1f(t2);
                t3 = t3 > 0.f ? t3 : expm1f(t3);
            }
            *(float4*)(crow + j) = make_float4(t0, t1, t2, t3);
        }
    }
}

// --------------------------------------------------------------------------
// In-place row softmax, row length 4096, one CTA (256 thr) per row.
// --------------------------------------------------------------------------
__global__ void softmax_inplace(float* __restrict__ E)
{
    float4* rp = (float4*)(E + (long long)blockIdx.x * NLSEQ);
    const int tid = threadIdx.x;
    __shared__ float red[256];

    float v[16];
    float m = -INFINITY;
    #pragma unroll
    for (int i = 0; i < 4; i++) {
        float4 x = rp[tid + i * 256];
        v[i * 4 + 0] = x.x; v[i * 4 + 1] = x.y;
        v[i * 4 + 2] = x.z; v[i * 4 + 3] = x.w;
        m = fmaxf(m, fmaxf(fmaxf(x.x, x.y), fmaxf(x.z, x.w)));
    }
    red[tid] = m;
    __syncthreads();
    for (int s = 128; s > 0; s >>= 1) {
        if (tid < s) red[tid] = fmaxf(red[tid], red[tid + s]);
        __syncthreads();
    }
    m = red[0];
    __syncthreads();

    float sum = 0.f;
    #pragma unroll
    for (int i = 0; i < 16; i++) {
        v[i] = expf(v[i] - m);
        sum += v[i];
    }
    red[tid] = sum;
    __syncthreads();
    for (int s = 128; s > 0; s >>= 1) {
        if (tid < s) red[tid] += red[tid + s];
        __syncthreads();
    }
    const float inv = 1.f / red[0];

    #pragma unroll
    for (int i = 0; i < 4; i++)
        rp[tid + i * 256] = make_float4(v[i * 4 + 0] * inv, v[i * 4 + 1] * inv,
                                        v[i * 4 + 2] * inv, v[i * 4 + 3] * inv);
}

// --------------------------------------------------------------------------
// Q2b[b,n,:] = Q2[n,:] + C1[b, map[n], :]   (grid: (NLBL, NB), 128 thr float4)
// --------------------------------------------------------------------------
__global__ void build_q2b(const float* __restrict__ Q2, const float* __restrict__ C1,
                          const int* __restrict__ cmap, float* __restrict__ q2b)
{
    const int n = blockIdx.x, b = blockIdx.y, t = threadIdx.x;
    const int c = cmap[n];
    const float4* q  = (const float4*)(Q2 + (long long)n * ND);
    const float4* cc = (const float4*)(C1 + ((long long)b * NCAT + c) * ND);
    float4*       o  = (float4*)(q2b + ((long long)b * NLBL + n) * ND);
    float4 a = q[t], d = cc[t];
    o[t] = make_float4(a.x + d.x, a.y + d.y, a.z + d.z, a.w + d.w);
}

// --------------------------------------------------------------------------
// Launch
// --------------------------------------------------------------------------
extern "C" void kernel_launch(void* const* d_in, const int* in_sizes, int n_in,
                              void* d_out, int out_size)
{
    const float* H    = (const float*)d_in[0];   // [B, d, L]
    const float* Wk   = (const float*)d_in[1];   // [d, d]
    const float* bk   = (const float*)d_in[2];   // [d]
    const float* Wv   = (const float*)d_in[3];   // [d, d]
    const float* bv   = (const float*)d_in[4];   // [d]
    const float* Q1   = (const float*)d_in[5];   // [C1, d]
    const float* Q2   = (const float*)d_in[6];   // [Lbl, d]
    const int*   cmap = (const int*)d_in[7];     // [Lbl]
    (void)in_sizes; (void)n_in; (void)out_size;

    float *Kp, *Vp, *E1p, *C1p, *Q2bp;
    cudaGetSymbolAddress((void**)&Kp,   g_K);
    cudaGetSymbolAddress((void**)&Vp,   g_V);
    cudaGetSymbolAddress((void**)&E1p,  g_E1);
    cudaGetSymbolAddress((void**)&C1p,  g_C1);
    cudaGetSymbolAddress((void**)&Q2bp, g_Q2b);

    float* outC2 = (float*)d_out;                                   // [B, Lbl, d]
    float* outA2 = (float*)d_out + (long long)NB * NLBL * ND;       // [B, Lbl, L]

    const float inv_scale = 1.0f / sqrtf(512.0f);
    const long long sKV = (long long)ND * NLSEQ;

    // 1) Kt = elu(Wk @ H_b + bk), Vt likewise.  C: [d, L] per b (NN)
    {
        dim3 grid(NLSEQ / BN, ND / BM, NB);
        sgemm<false><<<grid, 256>>>(Wk, H, Kp, ND, NLSEQ, ND, ND, NLSEQ, NLSEQ,
                                    0, sKV, sKV, 1.f, bk, 2);
        sgemm<false><<<grid, 256>>>(Wv, H, Vp, ND, NLSEQ, ND, ND, NLSEQ, NLSEQ,
                                    0, sKV, sKV, 1.f, bv, 2);
    }
    // 2) E1 = (Q1 @ Kt) / SCALE   [NCAT, L] per b (NN)
    {
        dim3 grid(NLSEQ / BN, (NCAT + BM - 1) / BM, NB);
        sgemm<false><<<grid, 256>>>(Q1, Kp, E1p, NCAT, NLSEQ, ND, ND, NLSEQ, NLSEQ,
                                    0, sKV, (long long)NCAT * NLSEQ,
                                    inv_scale, nullptr, 1);
    }
    // 3) A1 = softmax(E1) in place
    softmax_inplace<<<NB * NCAT, 256>>>(E1p);
    // 4) C1 = A1 @ Vt^T   [NCAT, d] per b (NT)
    {
        dim3 grid(ND / BN, (NCAT + BM - 1) / BM, NB);
        sgemm<true><<<grid, 256>>>(E1p, Vp, C1p, NCAT, ND, NLSEQ,
                                   NLSEQ, NLSEQ, ND,
                                   (long long)NCAT * NLSEQ, sKV,
                                   (long long)NCAT * ND, 1.f, nullptr, 0);
    }
    // 5) Q2b = Q2 + C1[gather]
    build_q2b<<<dim3(NLBL, NB), 128>>>(Q2, C1p, cmap, Q2bp);
    // 6) E2 = (Q2b @ Kt)/SCALE -> written straight into A2 output region (NN)
    {
        dim3 grid(NLSEQ / BN, (NLBL + BM - 1) / BM, NB);
        sgemm<false><<<grid, 256>>>(Q2bp, Kp, outA2, NLBL, NLSEQ, ND,
                                    ND, NLSEQ, NLSEQ,
                                    (long long)NLBL * ND, sKV,
                                    (long long)NLBL * NLSEQ,
                                    inv_scale, nullptr, 1);
    }
    // 7) A2 = softmax(E2) in place (this IS the second output)
    softmax_inplace<<<NB * NLBL, 256>>>(outA2);
    // 8) C2 = A2 @ Vt^T   [NLBL, d] per b (NT)
    {
        dim3 grid(ND / BN, (NLBL + BM - 1) / BM, NB);
        sgemm<true><<<grid, 256>>>(outA2, Vp, outC2, NLBL, ND, NLSEQ,
                                   NLSEQ, NLSEQ, ND,
                                   (long long)NLBL * NLSEQ, sKV,
                                   (long long)NLBL * ND, 1.f, nullptr, 0);
    }
}

// round 11
// speedup vs baseline: 2.5416x; 2.5413x over previous
#include <cuda_runtime.h>
#include <cuda_bf16.h>
#include <math.h>
#include <stdint.h>

typedef __nv_bfloat16 bf16;

#define NB 4
#define ND 512
#define NLSEQ 4096
#define NCAT 1168
#define NLBL 8929

// ---------------- scratch (device globals; allocation-free) ----------------
__device__ __align__(256) bf16 g_Hh [(size_t)NB * ND * NLSEQ];
__device__ __align__(256) bf16 g_Hl [(size_t)NB * ND * NLSEQ];
__device__ __align__(256) bf16 g_Wkh[ND * ND];
__device__ __align__(256) bf16 g_Wkl[ND * ND];
__device__ __align__(256) bf16 g_Wvh[ND * ND];
__device__ __align__(256) bf16 g_Wvl[ND * ND];
__device__ __align__(256) bf16 g_Q1h[NCAT * ND];
__device__ __align__(256) bf16 g_Q1l[NCAT * ND];
__device__ __align__(256) bf16 g_Kh [(size_t)NB * ND * NLSEQ];
__device__ __align__(256) bf16 g_Kl [(size_t)NB * ND * NLSEQ];
__device__ __align__(256) bf16 g_Vh [(size_t)NB * ND * NLSEQ];
__device__ __align__(256) bf16 g_Vl [(size_t)NB * ND * NLSEQ];
__device__ __align__(256) float g_E1[(size_t)NB * NCAT * NLSEQ];
__device__ __align__(256) bf16 g_A1h[(size_t)NB * NCAT * NLSEQ];
__device__ __align__(256) bf16 g_A1l[(size_t)NB * NCAT * NLSEQ];
__device__ __align__(256) float g_C1[(size_t)NB * NCAT * ND];
__device__ __align__(256) bf16 g_Q2bh[(size_t)NB * NLBL * ND];
__device__ __align__(256) bf16 g_Q2bl[(size_t)NB * NLBL * ND];
__device__ __align__(256) bf16 g_A2h[(size_t)NB * NLBL * NLSEQ];
__device__ __align__(256) bf16 g_A2l[(size_t)NB * NLBL * NLSEQ];

// ---------------- PTX helpers ----------------
__device__ __forceinline__ void cp16(uint32_t dst, const void* src, int sz) {
    asm volatile("cp.async.cg.shared.global [%0], [%1], 16, %2;\n"
                 :: "r"(dst), "l"(src), "r"(sz));
}
__device__ __forceinline__ void ldsm4(uint32_t (&r)[4], uint32_t a) {
    asm volatile("ldmatrix.sync.aligned.m8n8.x4.shared.b16 {%0,%1,%2,%3}, [%4];"
                 : "=r"(r[0]), "=r"(r[1]), "=r"(r[2]), "=r"(r[3]) : "r"(a));
}
__device__ __forceinline__ void ldsm4t(uint32_t (&r)[4], uint32_t a) {
    asm volatile("ldmatrix.sync.aligned.m8n8.x4.trans.shared.b16 {%0,%1,%2,%3}, [%4];"
                 : "=r"(r[0]), "=r"(r[1]), "=r"(r[2]), "=r"(r[3]) : "r"(a));
}
__device__ __forceinline__ void mma16816(float (&d)[4], const uint32_t (&a)[4],
                                         uint32_t b0, uint32_t b1) {
    asm volatile("mma.sync.aligned.m16n8k16.row.col.f32.bf16.bf16.f32 "
                 "{%0,%1,%2,%3}, {%4,%5,%6,%7}, {%8,%9}, {%0,%1,%2,%3};"
                 : "+f"(d[0]), "+f"(d[1]), "+f"(d[2]), "+f"(d[3])
                 : "r"(a[0]), "r"(a[1]), "r"(a[2]), "r"(a[3]), "r"(b0), "r"(b1));
}
__device__ __forceinline__ void split2(float a, float b, uint32_t& h, uint32_t& l) {
    __nv_bfloat16 ha = __float2bfloat16_rn(a), hb = __float2bfloat16_rn(b);
    float la = a - __bfloat162float(ha), lb = b - __bfloat162float(hb);
    __nv_bfloat162 H; H.x = ha; H.y = hb;
    __nv_bfloat162 L = __floats2bfloat162_rn(la, lb);
    h = *reinterpret_cast<uint32_t*>(&H);
    l = *reinterpret_cast<uint32_t*>(&L);
}

// ---------------------------------------------------------------------------
// bf16x3 tensor-core GEMM.  C = sum_k (Ah+Al)(Bh+Bl) dropping lo*lo.
//   BT=false: B is [K,N] row-major (NN).  BT=true: B is [N,K] row-major (NT).
//   EPI=0: fp32 out = acc*alpha.  EPI=1: +bias[row], ELU, bf16 hi/lo out.
// CTA 128x128 k-step 32, 256 thr, warps 2(m)x4(n) of 64x32, m16n8k16 mma.
// Single-buffered static smem (<=48KB), 2 CTAs/SM hide load latency.
// ---------------------------------------------------------------------------
template<bool BT, int EPI>
__global__ __launch_bounds__(256, 2)
void mma_gemm(const bf16* __restrict__ Agh, const bf16* __restrict__ Agl,
              const bf16* __restrict__ Bgh, const bf16* __restrict__ Bgl,
              float* __restrict__ Cf, bf16* __restrict__ Coh, bf16* __restrict__ Col,
              int M, int N, int K, int lda, int ldb, int ldc,
              long long sA, long long sB, long long sC,
              float alpha, const float* __restrict__ bias)
{
    constexpr int ATILE = 128 * 40;                    // elems, 80B rows
    constexpr int BTILE = BT ? 128 * 40 : 32 * 136;    // 80B / 272B rows
    __shared__ bf16 sAh[ATILE], sAl[ATILE], sBh[BTILE], sBl[BTILE];

    const uint32_t bAh = (uint32_t)__cvta_generic_to_shared(sAh);
    const uint32_t bAl = (uint32_t)__cvta_generic_to_shared(sAl);
    const uint32_t bBh = (uint32_t)__cvta_generic_to_shared(sBh);
    const uint32_t bBl = (uint32_t)__cvta_generic_to_shared(sBl);

    const int tid = threadIdx.x, lane = tid & 31, warp = tid >> 5;
    const int wm = warp >> 2, wn = warp & 3;
    const int z = blockIdx.z;
    const int m0 = blockIdx.y * 128, n0 = blockIdx.x * 128;

    const bf16* Ah = Agh + (long long)z * sA;
    const bf16* Al = Agl + (long long)z * sA;
    const bf16* Bh = Bgh + (long long)z * sB;
    const bf16* Bl = Bgl + (long long)z * sB;

    float acc[4][4][4];
    #pragma unroll
    for (int i = 0; i < 4; i++)
        #pragma unroll
        for (int j = 0; j < 4; j++)
            #pragma unroll
            for (int q = 0; q < 4; q++) acc[i][j][q] = 0.f;

    // lane-constant LDSM offsets (bytes)
    const uint32_t aLane = ((uint32_t)(wm * 64 + (lane & 15)) * 40
                            + ((lane >> 4) << 3)) * 2;
    uint32_t bLane;
    if (BT)
        bLane = ((uint32_t)(wn * 32 + (lane & 7) + ((lane >> 4) << 3)) * 40
                 + (lane & 8)) * 2;
    else
        bLane = ((uint32_t)((lane & 7) + (lane & 8)) * 136
                 + wn * 32 + ((lane >> 4) << 3)) * 2;

    const int iters = K >> 5;
    for (int it = 0; it < iters; it++) {
        const int k0 = it << 5;
        // ---- fill (cp.async): A hi+lo, B hi+lo ----
        #pragma unroll
        for (int i = 0; i < 2; i++) {
            int c = tid * 2 + i, row = c >> 2, kc = (c & 3) * 8;
            int grow = m0 + row;
            int sz = (grow < M) ? 16 : 0;
            long long off = (long long)(sz ? grow : m0) * lda + k0 + kc;
            uint32_t d = (uint32_t)(row * 40 + kc) * 2;
            cp16(bAh + d, Ah + off, sz);
            cp16(bAl + d, Al + off, sz);
        }
        #pragma unroll
        for (int i = 0; i < 2; i++) {
            int c = tid * 2 + i;
            if (BT) {
                int row = c >> 2, kc = (c & 3) * 8;
                long long off = (long long)(n0 + row) * ldb + k0 + kc;
                uint32_t d = (uint32_t)(row * 40 + kc) * 2;
                cp16(bBh + d, Bh + off, 16);
                cp16(bBl + d, Bl + off, 16);
            } else {
                int kr = c >> 4, nc = (c & 15) * 8;
                long long off = (long long)(k0 + kr) * ldb + n0 + nc;
                uint32_t d = (uint32_t)(kr * 136 + nc) * 2;
                cp16(bBh + d, Bh + off, 16);
                cp16(bBl + d, Bl + off, 16);
            }
        }
        asm volatile("cp.async.commit_group;\ncp.async.wait_group 0;\n" ::: "memory");
        __syncthreads();

        // ---- compute: 2 x k16 micro-steps, 3 terms each ----
        #pragma unroll
        for (int kk = 0; kk < 2; kk++) {
            const uint32_t akk = kk * 32u;
            const uint32_t bkk = BT ? kk * 32u : kk * 4352u;

            uint32_t av[4][4], b2[2][4];
            #pragma unroll
            for (int mf = 0; mf < 4; mf++) ldsm4(av[mf], bAh + aLane + mf * 1280 + akk);
            #pragma unroll
            for (int p = 0; p < 2; p++) {
                uint32_t ad = bBh + bLane + bkk + (BT ? p * 1280u : p * 32u);
                if (BT) ldsm4(b2[p], ad); else ldsm4t(b2[p], ad);
            }
            #pragma unroll
            for (int mf = 0; mf < 4; mf++)               // Ah * Bh
                #pragma unroll
                for (int j = 0; j < 4; j++)
                    mma16816(acc[mf][j], av[mf], b2[j >> 1][(j & 1) * 2],
                             b2[j >> 1][(j & 1) * 2 + 1]);

            uint32_t c2[2][4];
            #pragma unroll
            for (int p = 0; p < 2; p++) {
                uint32_t ad = bBl + bLane + bkk + (BT ? p * 1280u : p * 32u);
                if (BT) ldsm4(c2[p], ad); else ldsm4t(c2[p], ad);
            }
            #pragma unroll
            for (int mf = 0; mf < 4; mf++)               // Ah * Bl
                #pragma unroll
                for (int j = 0; j < 4; j++)
                    mma16816(acc[mf][j], av[mf], c2[j >> 1][(j & 1) * 2],
                             c2[j >> 1][(j & 1) * 2 + 1]);

            #pragma unroll
            for (int mf = 0; mf < 4; mf++) ldsm4(av[mf], bAl + aLane + mf * 1280 + akk);
            #pragma unroll
            for (int mf = 0; mf < 4; mf++)               // Al * Bh
                #pragma unroll
                for (int j = 0; j < 4; j++)
                    mma16816(acc[mf][j], av[mf], b2[j >> 1][(j & 1) * 2],
                             b2[j >> 1][(j & 1) * 2 + 1]);
        }
        __syncthreads();
    }

    // ---- epilogue ----
    const long long cb = (long long)z * sC;
    #pragma unroll
    for (int mf = 0; mf < 4; mf++) {
        const int r0 = m0 + wm * 64 + mf * 16 + (lane >> 2);
        const int r1 = r0 + 8;
        #pragma unroll
        for (int j = 0; j < 4; j++) {
            const int cc = n0 + wn * 32 + j * 8 + (lane & 3) * 2;
            float* a4 = acc[mf][j];
            if (EPI == 0) {
                if (r0 < M)
                    *(float2*)(Cf + cb + (long long)r0 * ldc + cc) =
                        make_float2(a4[0] * alpha, a4[1] * alpha);
                if (r1 < M)
                    *(float2*)(Cf + cb + (long long)r1 * ldc + cc) =
                        make_float2(a4[2] * alpha, a4[3] * alpha);
            } else {
                if (r0 < M) {
                    float bv = bias[r0];
                    float x0 = a4[0] + bv; x0 = x0 > 0.f ? x0 : expm1f(x0);
                    float x1 = a4[1] + bv; x1 = x1 > 0.f ? x1 : expm1f(x1);
                    uint32_t h, l; split2(x0, x1, h, l);
                    *(uint32_t*)(Coh + cb + (long long)r0 * ldc + cc) = h;
                    *(uint32_t*)(Col + cb + (long long)r0 * ldc + cc) = l;
                }
                if (r1 < M) {
                    float bv = bias[r1];
                    float x0 = a4[2] + bv; x0 = x0 > 0.f ? x0 : expm1f(x0);
                    float x1 = a4[3] + bv; x1 = x1 > 0.f ? x1 : expm1f(x1);
                    uint32_t h, l; split2(x0, x1, h, l);
                    *(uint32_t*)(Coh + cb + (long long)r1 * ldc + cc) = h;
                    *(uint32_t*)(Col + cb + (long long)r1 * ldc + cc) = l;
                }
            }
        }
    }
}

// ---------------- fp32 -> bf16 hi/lo split ----------------
__global__ void cvt_split(const float4* __restrict__ x, uint32_t* __restrict__ h,
                          uint32_t* __restrict__ l, long long n4)
{
    long long i = (long long)blockIdx.x * blockDim.x + threadIdx.x;
    if (i >= n4) return;
    float4 v = x[i];
    uint32_t h01, l01, h23, l23;
    split2(v.x, v.y, h01, l01);
    split2(v.z, v.w, h23, l23);
    h[i * 2] = h01; h[i * 2 + 1] = h23;
    l[i * 2] = l01; l[i * 2 + 1] = l23;
}

// ---------------- softmax (len 4096); optional fp32 rewrite + bf16 split ---
__global__ void softmax_split(float* __restrict__ E, uint32_t* __restrict__ oh,
                              uint32_t* __restrict__ ol, int writef)
{
    const long long rbase = (long long)blockIdx.x * NLSEQ;
    float4* rp = (float4*)(E + rbase);
    const int tid = threadIdx.x;
    __shared__ float red[256];

    float v[16];
    float m = -INFINITY;
    #pragma unroll
    for (int i = 0; i < 4; i++) {
        float4 x = rp[tid + i * 256];
        v[i*4+0] = x.x; v[i*4+1] = x.y; v[i*4+2] = x.z; v[i*4+3] = x.w;
        m = fmaxf(m, fmaxf(fmaxf(x.x, x.y), fmaxf(x.z, x.w)));
    }
    red[tid] = m; __syncthreads();
    for (int s = 128; s > 0; s >>= 1) {
        if (tid < s) red[tid] = fmaxf(red[tid], red[tid + s]);
        __syncthreads();
    }
    m = red[0]; __syncthreads();

    float sum = 0.f;
    #pragma unroll
    for (int i = 0; i < 16; i++) { v[i] = expf(v[i] - m); sum += v[i]; }
    red[tid] = sum; __syncthreads();
    for (int s = 128; s > 0; s >>= 1) {
        if (tid < s) red[tid] += red[tid + s];
        __syncthreads();
    }
    const float inv = 1.f / red[0];

    uint32_t* ohr = oh + (rbase >> 1);
    uint32_t* olr = ol + (rbase >> 1);
    #pragma unroll
    for (int i = 0; i < 4; i++) {
        const int e4 = tid + i * 256;
        float p0 = v[i*4+0]*inv, p1 = v[i*4+1]*inv, p2 = v[i*4+2]*inv, p3 = v[i*4+3]*inv;
        if (writef) rp[e4] = make_float4(p0, p1, p2, p3);
        uint32_t h01, l01, h23, l23;
        split2(p0, p1, h01, l01);
        split2(p2, p3, h23, l23);
        ohr[e4*2] = h01; ohr[e4*2+1] = h23;
        olr[e4*2] = l01; olr[e4*2+1] = l23;
    }
}

// ---------------- Q2b = Q2 + C1[map], split to bf16 ----------------
__global__ void build_q2b(const float* __restrict__ Q2, const float* __restrict__ C1,
                          const int* __restrict__ cmap,
                          uint32_t* __restrict__ qh, uint32_t* __restrict__ ql)
{
    const int n = blockIdx.x, b = blockIdx.y, t = threadIdx.x;   // 128 thr
    const int c = cmap[n];
    const float4* q  = (const float4*)(Q2 + (long long)n * ND);
    const float4* cc = (const float4*)(C1 + ((long long)b * NCAT + c) * ND);
    const long long ob = ((long long)b * NLBL + n) * (ND / 2);
    float4 a = q[t], d = cc[t];
    uint32_t h01, l01, h23, l23;
    split2(a.x + d.x, a.y + d.y, h01, l01);
    split2(a.z + d.z, a.w + d.w, h23, l23);
    qh[ob + t*2] = h01; qh[ob + t*2 + 1] = h23;
    ql[ob + t*2] = l01; ql[ob + t*2 + 1] = l23;
}

// ---------------- launch ----------------
extern "C" void kernel_launch(void* const* d_in, const int* in_sizes, int n_in,
                              void* d_out, int out_size)
{
    const float* H    = (const float*)d_in[0];
    const float* Wk   = (const float*)d_in[1];
    const float* bk   = (const float*)d_in[2];
    const float* Wv   = (const float*)d_in[3];
    const float* bv   = (const float*)d_in[4];
    const float* Q1   = (const float*)d_in[5];
    const float* Q2   = (const float*)d_in[6];
    const int*   cmap = (const int*)d_in[7];
    (void)in_sizes; (void)n_in; (void)out_size;

    bf16 *Hh,*Hl,*Wkh,*Wkl,*Wvh,*Wvl,*Q1h,*Q1l,*Kh,*Kl,*Vh,*Vl;
    bf16 *A1h,*A1l,*Q2bh,*Q2bl,*A2h,*A2l;
    float *E1,*C1;
    cudaGetSymbolAddress((void**)&Hh,  g_Hh);  cudaGetSymbolAddress((void**)&Hl,  g_Hl);
    cudaGetSymbolAddress((void**)&Wkh, g_Wkh); cudaGetSymbolAddress((void**)&Wkl, g_Wkl);
    cudaGetSymbolAddress((void**)&Wvh, g_Wvh); cudaGetSymbolAddress((void**)&Wvl, g_Wvl);
    cudaGetSymbolAddress((void**)&Q1h, g_Q1h); cudaGetSymbolAddress((void**)&Q1l, g_Q1l);
    cudaGetSymbolAddress((void**)&Kh,  g_Kh);  cudaGetSymbolAddress((void**)&Kl,  g_Kl);
    cudaGetSymbolAddress((void**)&Vh,  g_Vh);  cudaGetSymbolAddress((void**)&Vl,  g_Vl);
    cudaGetSymbolAddress((void**)&E1,  g_E1);  cudaGetSymbolAddress((void**)&C1,  g_C1);
    cudaGetSymbolAddress((void**)&A1h, g_A1h); cudaGetSymbolAddress((void**)&A1l, g_A1l);
    cudaGetSymbolAddress((void**)&Q2bh,g_Q2bh);cudaGetSymbolAddress((void**)&Q2bl,g_Q2bl);
    cudaGetSymbolAddress((void**)&A2h, g_A2h); cudaGetSymbolAddress((void**)&A2l, g_A2l);

    float* outC2 = (float*)d_out;
    float* outA2 = (float*)d_out + (long long)NB * NLBL * ND;

    const float inv_scale = 1.0f / sqrtf(512.0f);
    const long long sKV = (long long)ND * NLSEQ;

    // 0) split inputs to bf16 hi/lo
    {
        long long n4 = (long long)NB * ND * NLSEQ / 4;
        cvt_split<<<(unsigned)((n4 + 255) / 256), 256>>>((const float4*)H,
            (uint32_t*)Hh, (uint32_t*)Hl, n4);
        long long w4 = (long long)ND * ND / 4;
        cvt_split<<<(unsigned)((w4 + 255) / 256), 256>>>((const float4*)Wk,
            (uint32_t*)Wkh, (uint32_t*)Wkl, w4);
        cvt_split<<<(unsigned)((w4 + 255) / 256), 256>>>((const float4*)Wv,
            (uint32_t*)Wvh, (uint32_t*)Wvl, w4);
        long long q4 = (long long)NCAT * ND / 4;
        cvt_split<<<(unsigned)((q4 + 255) / 256), 256>>>((const float4*)Q1,
            (uint32_t*)Q1h, (uint32_t*)Q1l, q4);
    }
    // 1) K/V = elu(W @ H + b) -> bf16 hi/lo  (NN, M=512 N=4096 K=512)
    {
        dim3 g(NLSEQ / 128, ND / 128, NB);
        mma_gemm<false,1><<<g, 256>>>(Wkh, Wkl, Hh, Hl, nullptr, Kh, Kl,
            ND, NLSEQ, ND, ND, NLSEQ, NLSEQ, 0, sKV, sKV, 1.f, bk);
        mma_gemm<false,1><<<g, 256>>>(Wvh, Wvl, Hh, Hl, nullptr, Vh, Vl,
            ND, NLSEQ, ND, ND, NLSEQ, NLSEQ, 0, sKV, sKV, 1.f, bv);
    }
    // 2) E1 = (Q1 @ K)/SCALE -> fp32   (NN, M=1168 N=4096 K=512)
    {
        dim3 g(NLSEQ / 128, (NCAT + 127) / 128, NB);
        mma_gemm<false,0><<<g, 256>>>(Q1h, Q1l, Kh, Kl, E1, nullptr, nullptr,
            NCAT, NLSEQ, ND, ND, NLSEQ, NLSEQ,
            0, sKV, (long long)NCAT * NLSEQ, inv_scale, nullptr);
    }
    // 3) A1 = softmax(E1) -> bf16 hi/lo
    softmax_split<<<NB * NCAT, 256>>>(E1, (uint32_t*)A1h, (uint32_t*)A1l, 0);
    // 4) C1 = A1 @ V^T -> fp32   (NT, M=1168 N=512 K=4096)
    {
        dim3 g(ND / 128, (NCAT + 127) / 128, NB);
        mma_gemm<true,0><<<g, 256>>>(A1h, A1l, Vh, Vl, C1, nullptr, nullptr,
            NCAT, ND, NLSEQ, NLSEQ, NLSEQ, ND,
            (long long)NCAT * NLSEQ, sKV, (long long)NCAT * ND, 1.f, nullptr);
    }
    // 5) Q2b = Q2 + C1[gather] -> bf16 hi/lo
    build_q2b<<<dim3(NLBL, NB), 128>>>(Q2, C1, cmap, (uint32_t*)Q2bh, (uint32_t*)Q2bl);
    // 6) E2 = (Q2b @ K)/SCALE -> fp32 straight into A2 output region
    {
        dim3 g(NLSEQ / 128, (NLBL + 127) / 128, NB);
        mma_gemm<false,0><<<g, 256>>>(Q2bh, Q2bl, Kh, Kl, outA2, nullptr, nullptr,
            NLBL, NLSEQ, ND, ND, NLSEQ, NLSEQ,
            (long long)NLBL * ND, sKV, (long long)NLBL * NLSEQ, inv_scale, nullptr);
    }
    // 7) A2 = softmax(E2): rewrite fp32 in place (output) + bf16 hi/lo for C2
    softmax_split<<<NB * NLBL, 256>>>(outA2, (uint32_t*)A2h, (uint32_t*)A2l, 1);
    // 8) C2 = A2 @ V^T -> fp32 output   (NT, M=8929 N=512 K=4096)
    {
        dim3 g(ND / 128, (NLBL + 127) / 128, NB);
        mma_gemm<true,0><<<g, 256>>>(A2h, A2l, Vh, Vl, outC2, nullptr, nullptr,
            NLBL, ND, NLSEQ, NLSEQ, NLSEQ, ND,
            (long long)NLBL * NLSEQ, sKV, (long long)NLBL * ND, 1.f, nullptr);
    }
}

// round 14
// speedup vs baseline: 2.6119x; 1.0277x over previous
#include <cuda_runtime.h>
#include <cuda_bf16.h>
#include <math.h>
#include <stdint.h>

typedef __nv_bfloat16 bf16;

#define NB 4
#define ND 512
#define NLSEQ 4096
#define NCAT 1168
#define NLBL 8929

// ---------------- scratch (device globals; allocation-free) ----------------
__device__ __align__(256) bf16 g_Hh [(size_t)NB * ND * NLSEQ];
__device__ __align__(256) bf16 g_Hl [(size_t)NB * ND * NLSEQ];
__device__ __align__(256) bf16 g_Wkh[ND * ND];
__device__ __align__(256) bf16 g_Wkl[ND * ND];
__device__ __align__(256) bf16 g_Wvh[ND * ND];
__device__ __align__(256) bf16 g_Wvl[ND * ND];
__device__ __align__(256) bf16 g_Q1h[NCAT * ND];
__device__ __align__(256) bf16 g_Q1l[NCAT * ND];
__device__ __align__(256) bf16 g_Kh [(size_t)NB * ND * NLSEQ];
__device__ __align__(256) bf16 g_Kl [(size_t)NB * ND * NLSEQ];
__device__ __align__(256) bf16 g_Vh [(size_t)NB * ND * NLSEQ];
__device__ __align__(256) bf16 g_Vl [(size_t)NB * ND * NLSEQ];
__device__ __align__(256) float g_E1[(size_t)NB * NCAT * NLSEQ];
__device__ __align__(256) bf16 g_A1h[(size_t)NB * NCAT * NLSEQ];
__device__ __align__(256) bf16 g_A1l[(size_t)NB * NCAT * NLSEQ];
__device__ __align__(256) float g_C1[(size_t)NB * NCAT * ND];
__device__ __align__(256) bf16 g_Q2bh[(size_t)NB * NLBL * ND];
__device__ __align__(256) bf16 g_Q2bl[(size_t)NB * NLBL * ND];
__device__ __align__(256) bf16 g_A2h[(size_t)NB * NLBL * NLSEQ];
__device__ __align__(256) bf16 g_A2l[(size_t)NB * NLBL * NLSEQ];

// ---------------- PTX helpers ----------------
__device__ __forceinline__ void cp16(uint32_t dst, const void* src, int sz) {
    asm volatile("cp.async.cg.shared.global [%0], [%1], 16, %2;\n"
                 :: "r"(dst), "l"(src), "r"(sz));
}
__device__ __forceinline__ void ldsm4(uint32_t (&r)[4], uint32_t a) {
    asm volatile("ldmatrix.sync.aligned.m8n8.x4.shared.b16 {%0,%1,%2,%3}, [%4];"
                 : "=r"(r[0]), "=r"(r[1]), "=r"(r[2]), "=r"(r[3]) : "r"(a));
}
__device__ __forceinline__ void ldsm4t(uint32_t (&r)[4], uint32_t a) {
    asm volatile("ldmatrix.sync.aligned.m8n8.x4.trans.shared.b16 {%0,%1,%2,%3}, [%4];"
                 : "=r"(r[0]), "=r"(r[1]), "=r"(r[2]), "=r"(r[3]) : "r"(a));
}
__device__ __forceinline__ void mma16816(float (&d)[4], const uint32_t (&a)[4],
                                         uint32_t b0, uint32_t b1) {
    asm volatile("mma.sync.aligned.m16n8k16.row.col.f32.bf16.bf16.f32 "
                 "{%0,%1,%2,%3}, {%4,%5,%6,%7}, {%8,%9}, {%0,%1,%2,%3};"
                 : "+f"(d[0]), "+f"(d[1]), "+f"(d[2]), "+f"(d[3])
                 : "r"(a[0]), "r"(a[1]), "r"(a[2]), "r"(a[3]), "r"(b0), "r"(b1));
}
__device__ __forceinline__ void split2(float a, float b, uint32_t& h, uint32_t& l) {
    __nv_bfloat16 ha = __float2bfloat16_rn(a), hb = __float2bfloat16_rn(b);
    float la = a - __bfloat162float(ha), lb = b - __bfloat162float(hb);
    __nv_bfloat162 H; H.x = ha; H.y = hb;
    __nv_bfloat162 L = __floats2bfloat162_rn(la, lb);
    h = *reinterpret_cast<uint32_t*>(&H);
    l = *reinterpret_cast<uint32_t*>(&L);
}

// ---------------------------------------------------------------------------
// bf16x3 tensor-core GEMM, 2-stage cp.async double-buffered pipeline.
//   C = sum_k (Ah+Al)(Bh+Bl) dropping lo*lo.
//   BT=false: B is [K,N] row-major (NN).  BT=true: B is [N,K] row-major (NT).
//   EPI=0: fp32 out = acc*alpha.  EPI=1: +bias[row], ELU, bf16 hi/lo out.
// CTA 128x128 k-step 32, 256 thr, warps 2(m)x4(n) of 64x32, m16n8k16 mma.
// Dynamic smem: 2 stages x (A hi/lo + B hi/lo); 2 CTAs/SM (regs capped 128).
// ---------------------------------------------------------------------------
template<bool BT, int EPI>
__global__ __launch_bounds__(256, 2)
void mma_gemm(const bf16* __restrict__ Agh, const bf16* __restrict__ Agl,
              const bf16* __restrict__ Bgh, const bf16* __restrict__ Bgl,
              float* __restrict__ Cf, bf16* __restrict__ Coh, bf16* __restrict__ Col,
              int M, int N, int K, int lda, int ldb, int ldc,
              long long sA, long long sB, long long sC,
              float alpha, const float* __restrict__ bias)
{
    constexpr int A_T = 128 * 40;                      // elems; 80B rows
    constexpr int B_T = BT ? 128 * 40 : 32 * 136;      // 80B / 272B rows
    constexpr int STAGE = 2 * A_T + 2 * B_T;           // elems per stage
    extern __shared__ bf16 dynsm[];
    const uint32_t sb = (uint32_t)__cvta_generic_to_shared(dynsm);

    const int tid = threadIdx.x, lane = tid & 31, warp = tid >> 5;
    const int wm = warp >> 2, wn = warp & 3;
    const int z = blockIdx.z;
    const int m0 = blockIdx.y * 128, n0 = blockIdx.x * 128;

    const bf16* Ah = Agh + (long long)z * sA;
    const bf16* Al = Agl + (long long)z * sA;
    const bf16* Bh = Bgh + (long long)z * sB;
    const bf16* Bl = Bgl + (long long)z * sB;

    float acc[4][4][4];
    #pragma unroll
    for (int i = 0; i < 4; i++)
        #pragma unroll
        for (int j = 0; j < 4; j++)
            #pragma unroll
            for (int q = 0; q < 4; q++) acc[i][j][q] = 0.f;

    // lane-constant LDSM offsets (bytes, relative to stage base)
    const uint32_t aLane = ((uint32_t)(wm * 64 + (lane & 15)) * 40
                            + ((lane >> 4) << 3)) * 2;
    uint32_t bLane;
    if (BT)
        bLane = ((uint32_t)(wn * 32 + (lane & 7) + ((lane >> 4) << 3)) * 40
                 + (lane & 8)) * 2;
    else
        bLane = ((uint32_t)((lane & 7) + (lane & 8)) * 136
                 + wn * 32 + ((lane >> 4) << 3)) * 2;

    // ---- fill one stage with cp.async ----
    auto fill = [&](int st, int k0) {
        const uint32_t base = sb + (uint32_t)(st * STAGE) * 2;
        #pragma unroll
        for (int i = 0; i < 2; i++) {
            int c = tid * 2 + i, row = c >> 2, kc = (c & 3) * 8;
            int grow = m0 + row;
            int sz = (grow < M) ? 16 : 0;
            long long off = (long long)(sz ? grow : m0) * lda + k0 + kc;
            uint32_t d = base + (uint32_t)(row * 40 + kc) * 2;
            cp16(d, Ah + off, sz);
            cp16(d + (uint32_t)A_T * 2, Al + off, sz);
        }
        #pragma unroll
        for (int i = 0; i < 2; i++) {
            int c = tid * 2 + i;
            if (BT) {
                int row = c >> 2, kc = (c & 3) * 8;
                long long off = (long long)(n0 + row) * ldb + k0 + kc;
                uint32_t d = base + (uint32_t)(2 * A_T + row * 40 + kc) * 2;
                cp16(d, Bh + off, 16);
                cp16(d + (uint32_t)B_T * 2, Bl + off, 16);
            } else {
                int kr = c >> 4, nc = (c & 15) * 8;
                long long off = (long long)(k0 + kr) * ldb + n0 + nc;
                uint32_t d = base + (uint32_t)(2 * A_T + kr * 136 + nc) * 2;
                cp16(d, Bh + off, 16);
                cp16(d + (uint32_t)B_T * 2, Bl + off, 16);
            }
        }
        asm volatile("cp.async.commit_group;\n" ::: "memory");
    };

    const int iters = K >> 5;
    fill(0, 0);
    int buf = 0;

    for (int it = 0; it < iters; it++) {
        if (it + 1 < iters) {
            fill(buf ^ 1, (it + 1) << 5);
            asm volatile("cp.async.wait_group 1;\n" ::: "memory");
        } else {
            asm volatile("cp.async.wait_group 0;\n" ::: "memory");
        }
        __syncthreads();

        const uint32_t stb = sb + (uint32_t)(buf * STAGE) * 2;
        const uint32_t bAh = stb + aLane;
        const uint32_t bAl = stb + (uint32_t)A_T * 2 + aLane;
        const uint32_t bBh = stb + (uint32_t)(2 * A_T) * 2 + bLane;
        const uint32_t bBl = bBh + (uint32_t)B_T * 2;

        #pragma unroll
        for (int kk = 0; kk < 2; kk++) {
            const uint32_t akk = kk * 32u;
            const uint32_t bkk = BT ? kk * 32u : kk * 4352u;

            uint32_t av[4][4], b2[2][4];
            #pragma unroll
            for (int mf = 0; mf < 4; mf++) ldsm4(av[mf], bAh + mf * 1280 + akk);
            #pragma unroll
            for (int p = 0; p < 2; p++) {
                uint32_t ad = bBh + bkk + (BT ? p * 1280u : p * 32u);
                if (BT) ldsm4(b2[p], ad); else ldsm4t(b2[p], ad);
            }
            #pragma unroll
            for (int mf = 0; mf < 4; mf++)               // Ah * Bh
                #pragma unroll
                for (int j = 0; j < 4; j++)
                    mma16816(acc[mf][j], av[mf], b2[j >> 1][(j & 1) * 2],
                             b2[j >> 1][(j & 1) * 2 + 1]);

            uint32_t c2[2][4];
            #pragma unroll
            for (int p = 0; p < 2; p++) {
                uint32_t ad = bBl + bkk + (BT ? p * 1280u : p * 32u);
                if (BT) ldsm4(c2[p], ad); else ldsm4t(c2[p], ad);
            }
            #pragma unroll
            for (int mf = 0; mf < 4; mf++)               // Ah * Bl
                #pragma unroll
                for (int j = 0; j < 4; j++)
                    mma16816(acc[mf][j], av[mf], c2[j >> 1][(j & 1) * 2],
                             c2[j >> 1][(j & 1) * 2 + 1]);

            #pragma unroll
            for (int mf = 0; mf < 4; mf++) ldsm4(av[mf], bAl + mf * 1280 + akk);
            #pragma unroll
            for (int mf = 0; mf < 4; mf++)               // Al * Bh
                #pragma unroll
                for (int j = 0; j < 4; j++)
                    mma16816(acc[mf][j], av[mf], b2[j >> 1][(j & 1) * 2],
                             b2[j >> 1][(j & 1) * 2 + 1]);
        }
        __syncthreads();   // readers done before this buffer is refilled
        buf ^= 1;
    }

    // ---- epilogue ----
    const long long cb = (long long)z * sC;
    #pragma unroll
    for (int mf = 0; mf < 4; mf++) {
        const int r0 = m0 + wm * 64 + mf * 16 + (lane >> 2);
        const int r1 = r0 + 8;
        #pragma unroll
        for (int j = 0; j < 4; j++) {
            const int cc = n0 + wn * 32 + j * 8 + (lane & 3) * 2;
            float* a4 = acc[mf][j];
            if (EPI == 0) {
                if (r0 < M)
                    *(float2*)(Cf + cb + (long long)r0 * ldc + cc) =
                        make_float2(a4[0] * alpha, a4[1] * alpha);
                if (r1 < M)
                    *(float2*)(Cf + cb + (long long)r1 * ldc + cc) =
                        make_float2(a4[2] * alpha, a4[3] * alpha);
            } else {
                if (r0 < M) {
                    float bv = bias[r0];
                    float x0 = a4[0] + bv; x0 = x0 > 0.f ? x0 : expm1f(x0);
                    float x1 = a4[1] + bv; x1 = x1 > 0.f ? x1 : expm1f(x1);
                    uint32_t h, l; split2(x0, x1, h, l);
                    *(uint32_t*)(Coh + cb + (long long)r0 * ldc + cc) = h;
                    *(uint32_t*)(Col + cb + (long long)r0 * ldc + cc) = l;
                }
                if (r1 < M) {
                    float bv = bias[r1];
                    float x0 = a4[2] + bv; x0 = x0 > 0.f ? x0 : expm1f(x0);
                    float x1 = a4[3] + bv; x1 = x1 > 0.f ? x1 : expm1f(x1);
                    uint32_t h, l; split2(x0, x1, h, l);
                    *(uint32_t*)(Coh + cb + (long long)r1 * ldc + cc) = h;
                    *(uint32_t*)(Col + cb + (long long)r1 * ldc + cc) = l;
                }
            }
        }
    }
}

// ---------------- fp32 -> bf16 hi/lo split ----------------
__global__ void cvt_split(const float4* __restrict__ x, uint32_t* __restrict__ h,
                          uint32_t* __restrict__ l, long long n4)
{
    long long i = (long long)blockIdx.x * blockDim.x + threadIdx.x;
    if (i >= n4) return;
    float4 v = x[i];
    uint32_t h01, l01, h23, l23;
    split2(v.x, v.y, h01, l01);
    split2(v.z, v.w, h23, l23);
    h[i * 2] = h01; h[i * 2 + 1] = h23;
    l[i * 2] = l01; l[i * 2 + 1] = l23;
}

// ---------------- softmax (len 4096); optional fp32 rewrite + bf16 split ---
__global__ void softmax_split(float* __restrict__ E, uint32_t* __restrict__ oh,
                              uint32_t* __restrict__ ol, int writef)
{
    const long long rbase = (long long)blockIdx.x * NLSEQ;
    float4* rp = (float4*)(E + rbase);
    const int tid = threadIdx.x;
    __shared__ float red[256];

    float v[16];
    float m = -INFINITY;
    #pragma unroll
    for (int i = 0; i < 4; i++) {
        float4 x = rp[tid + i * 256];
        v[i*4+0] = x.x; v[i*4+1] = x.y; v[i*4+2] = x.z; v[i*4+3] = x.w;
        m = fmaxf(m, fmaxf(fmaxf(x.x, x.y), fmaxf(x.z, x.w)));
    }
    red[tid] = m; __syncthreads();
    for (int s = 128; s > 0; s >>= 1) {
        if (tid < s) red[tid] = fmaxf(red[tid], red[tid + s]);
        __syncthreads();
    }
    m = red[0]; __syncthreads();

    float sum = 0.f;
    #pragma unroll
    for (int i = 0; i < 16; i++) { v[i] = expf(v[i] - m); sum += v[i]; }
    red[tid] = sum; __syncthreads();
    for (int s = 128; s > 0; s >>= 1) {
        if (tid < s) red[tid] += red[tid + s];
        __syncthreads();
    }
    const float inv = 1.f / red[0];

    uint32_t* ohr = oh + (rbase >> 1);
    uint32_t* olr = ol + (rbase >> 1);
    #pragma unroll
    for (int i = 0; i < 4; i++) {
        const int e4 = tid + i * 256;
        float p0 = v[i*4+0]*inv, p1 = v[i*4+1]*inv, p2 = v[i*4+2]*inv, p3 = v[i*4+3]*inv;
        if (writef) rp[e4] = make_float4(p0, p1, p2, p3);
        uint32_t h01, l01, h23, l23;
        split2(p0, p1, h01, l01);
        split2(p2, p3, h23, l23);
        ohr[e4*2] = h01; ohr[e4*2+1] = h23;
        olr[e4*2] = l01; olr[e4*2+1] = l23;
    }
}

// ---------------- Q2b = Q2 + C1[map], split to bf16 ----------------
__global__ void build_q2b(const float* __restrict__ Q2, const float* __restrict__ C1,
                          const int* __restrict__ cmap,
                          uint32_t* __restrict__ qh, uint32_t* __restrict__ ql)
{
    const int n = blockIdx.x, b = blockIdx.y, t = threadIdx.x;   // 128 thr
    const int c = cmap[n];
    const float4* q  = (const float4*)(Q2 + (long long)n * ND);
    const float4* cc = (const float4*)(C1 + ((long long)b * NCAT + c) * ND);
    const long long ob = ((long long)b * NLBL + n) * (ND / 2);
    float4 a = q[t], d = cc[t];
    uint32_t h01, l01, h23, l23;
    split2(a.x + d.x, a.y + d.y, h01, l01);
    split2(a.z + d.z, a.w + d.w, h23, l23);
    qh[ob + t*2] = h01; qh[ob + t*2 + 1] = h23;
    ql[ob + t*2] = l01; ql[ob + t*2 + 1] = l23;
}

// ---------------- launch ----------------
extern "C" void kernel_launch(void* const* d_in, const int* in_sizes, int n_in,
                              void* d_out, int out_size)
{
    const float* H    = (const float*)d_in[0];
    const float* Wk   = (const float*)d_in[1];
    const float* bk   = (const float*)d_in[2];
    const float* Wv   = (const float*)d_in[3];
    const float* bv   = (const float*)d_in[4];
    const float* Q1   = (const float*)d_in[5];
    const float* Q2   = (const float*)d_in[6];
    const int*   cmap = (const int*)d_in[7];
    (void)in_sizes; (void)n_in; (void)out_size;

    bf16 *Hh,*Hl,*Wkh,*Wkl,*Wvh,*Wvl,*Q1h,*Q1l,*Kh,*Kl,*Vh,*Vl;
    bf16 *A1h,*A1l,*Q2bh,*Q2bl,*A2h,*A2l;
    float *E1,*C1;
    cudaGetSymbolAddress((void**)&Hh,  g_Hh);  cudaGetSymbolAddress((void**)&Hl,  g_Hl);
    cudaGetSymbolAddress((void**)&Wkh, g_Wkh); cudaGetSymbolAddress((void**)&Wkl, g_Wkl);
    cudaGetSymbolAddress((void**)&Wvh, g_Wvh); cudaGetSymbolAddress((void**)&Wvl, g_Wvl);
    cudaGetSymbolAddress((void**)&Q1h, g_Q1h); cudaGetSymbolAddress((void**)&Q1l, g_Q1l);
    cudaGetSymbolAddress((void**)&Kh,  g_Kh);  cudaGetSymbolAddress((void**)&Kl,  g_Kl);
    cudaGetSymbolAddress((void**)&Vh,  g_Vh);  cudaGetSymbolAddress((void**)&Vl,  g_Vl);
    cudaGetSymbolAddress((void**)&E1,  g_E1);  cudaGetSymbolAddress((void**)&C1,  g_C1);
    cudaGetSymbolAddress((void**)&A1h, g_A1h); cudaGetSymbolAddress((void**)&A1l, g_A1l);
    cudaGetSymbolAddress((void**)&Q2bh,g_Q2bh);cudaGetSymbolAddress((void**)&Q2bl,g_Q2bl);
    cudaGetSymbolAddress((void**)&A2h, g_A2h); cudaGetSymbolAddress((void**)&A2l, g_A2l);

    float* outC2 = (float*)d_out;
    float* outA2 = (float*)d_out + (long long)NB * NLBL * ND;

    const float inv_scale = 1.0f / sqrtf(512.0f);
    const long long sKV = (long long)ND * NLSEQ;

    // dynamic smem opt-in (2-stage pipeline buffers)
    const int smemNN = 2 * (2 * 128 * 40 + 2 * 32 * 136) * 2;   // 75776 B
    const int smemNT = 2 * (4 * 128 * 40) * 2;                  // 81920 B
    cudaFuncSetAttribute(mma_gemm<false,1>,
        cudaFuncAttributeMaxDynamicSharedMemorySize, smemNN);
    cudaFuncSetAttribute(mma_gemm<false,0>,
        cudaFuncAttributeMaxDynamicSharedMemorySize, smemNN);
    cudaFuncSetAttribute(mma_gemm<true,0>,
        cudaFuncAttributeMaxDynamicSharedMemorySize, smemNT);

    // 0) split inputs to bf16 hi/lo
    {
        long long n4 = (long long)NB * ND * NLSEQ / 4;
        cvt_split<<<(unsigned)((n4 + 255) / 256), 256>>>((const float4*)H,
            (uint32_t*)Hh, (uint32_t*)Hl, n4);
        long long w4 = (long long)ND * ND / 4;
        cvt_split<<<(unsigned)((w4 + 255) / 256), 256>>>((const float4*)Wk,
            (uint32_t*)Wkh, (uint32_t*)Wkl, w4);
        cvt_split<<<(unsigned)((w4 + 255) / 256), 256>>>((const float4*)Wv,
            (uint32_t*)Wvh, (uint32_t*)Wvl, w4);
        long long q4 = (long long)NCAT * ND / 4;
        cvt_split<<<(unsigned)((q4 + 255) / 256), 256>>>((const float4*)Q1,
            (uint32_t*)Q1h, (uint32_t*)Q1l, q4);
    }
    // 1) K/V = elu(W @ H + b) -> bf16 hi/lo  (NN, M=512 N=4096 K=512)
    {
        dim3 g(NLSEQ / 128, ND / 128, NB);
        mma_gemm<false,1><<<g, 256, smemNN>>>(Wkh, Wkl, Hh, Hl, nullptr, Kh, Kl,
            ND, NLSEQ, ND, ND, NLSEQ, NLSEQ, 0, sKV, sKV, 1.f, bk);
        mma_gemm<false,1><<<g, 256, smemNN>>>(Wvh, Wvl, Hh, Hl, nullptr, Vh, Vl,
            ND, NLSEQ, ND, ND, NLSEQ, NLSEQ, 0, sKV, sKV, 1.f, bv);
    }
    // 2) E1 = (Q1 @ K)/SCALE -> fp32   (NN, M=1168 N=4096 K=512)
    {
        dim3 g(NLSEQ / 128, (NCAT + 127) / 128, NB);
        mma_gemm<false,0><<<g, 256, smemNN>>>(Q1h, Q1l, Kh, Kl, E1, nullptr, nullptr,
            NCAT, NLSEQ, ND, ND, NLSEQ, NLSEQ,
            0, sKV, (long long)NCAT * NLSEQ, inv_scale, nullptr);
    }
    // 3) A1 = softmax(E1) -> bf16 hi/lo
    softmax_split<<<NB * NCAT, 256>>>(E1, (uint32_t*)A1h, (uint32_t*)A1l, 0);
    // 4) C1 = A1 @ V^T -> fp32   (NT, M=1168 N=512 K=4096)
    {
        dim3 g(ND / 128, (NCAT + 127) / 128, NB);
        mma_gemm<true,0><<<g, 256, smemNT>>>(A1h, A1l, Vh, Vl, C1, nullptr, nullptr,
            NCAT, ND, NLSEQ, NLSEQ, NLSEQ, ND,
            (long long)NCAT * NLSEQ, sKV, (long long)NCAT * ND, 1.f, nullptr);
    }
    // 5) Q2b = Q2 + C1[gather] -> bf16 hi/lo
    build_q2b<<<dim3(NLBL, NB), 128>>>(Q2, C1, cmap, (uint32_t*)Q2bh, (uint32_t*)Q2bl);
    // 6) E2 = (Q2b @ K)/SCALE -> fp32 straight into A2 output region
    {
        dim3 g(NLSEQ / 128, (NLBL + 127) / 128, NB);
        mma_gemm<false,0><<<g, 256, smemNN>>>(Q2bh, Q2bl, Kh, Kl, outA2, nullptr, nullptr,
            NLBL, NLSEQ, ND, ND, NLSEQ, NLSEQ,
            (long long)NLBL * ND, sKV, (long long)NLBL * NLSEQ, inv_scale, nullptr);
    }
    // 7) A2 = softmax(E2): rewrite fp32 in place (output) + bf16 hi/lo for C2
    softmax_split<<<NB * NLBL, 256>>>(outA2, (uint32_t*)A2h, (uint32_t*)A2l, 1);
    // 8) C2 = A2 @ V^T -> fp32 output   (NT, M=8929 N=512 K=4096)
    {
        dim3 g(ND / 128, (NLBL + 127) / 128, NB);
        mma_gemm<true,0><<<g, 256, smemNT>>>(A2h, A2l, Vh, Vl, outC2, nullptr, nullptr,
            NLBL, ND, NLSEQ, NLSEQ, NLSEQ, ND,
            (long long)NLBL * NLSEQ, sKV, (long long)NLBL * ND, 1.f, nullptr);
    }
}